// round 1
// baseline (speedup 1.0000x reference)
#include <cuda_runtime.h>
#include <math.h>

#define BATCH 4096
#define DIM   512
#define NCLS  10

#define BM 128
#define BN 128
#define BK 16
#define SPAD 4   // smem row padding (floats)

// Scratch (device globals -- no allocation allowed)
__device__ float g_normf[BATCH * DIM];   // normalized features, 8 MB
__device__ int   g_cls[BATCH];
__device__ float g_pos[BATCH];
__device__ float g_all[BATCH];

// ---------------------------------------------------------------------------
// packed f32x2 helpers (FFMA2 path: ptxas never emits it from C++, only PTX)
// ---------------------------------------------------------------------------
__device__ __forceinline__ unsigned long long pack2(float x, float y) {
    unsigned long long r;
    asm("mov.b64 %0, {%1, %2};"
        : "=l"(r) : "r"(__float_as_uint(x)), "r"(__float_as_uint(y)));
    return r;
}
__device__ __forceinline__ void fma2(unsigned long long& d,
                                     unsigned long long a,
                                     unsigned long long b) {
    asm("fma.rn.f32x2 %0, %1, %2, %0;" : "+l"(d) : "l"(a), "l"(b));
}
__device__ __forceinline__ void unpack2(unsigned long long v, float& lo, float& hi) {
    unsigned int a, b;
    asm("mov.b64 {%0, %1}, %2;" : "=r"(a), "=r"(b) : "l"(v));
    lo = __uint_as_float(a);
    hi = __uint_as_float(b);
}

// ---------------------------------------------------------------------------
// Kernel 1: L2-normalize rows, extract class id, zero accumulators
// grid = BATCH blocks of 128 threads (each thread owns one float4 of the row)
// ---------------------------------------------------------------------------
__global__ void normalize_kernel(const float* __restrict__ feats,
                                 const float* __restrict__ labels) {
    int row = blockIdx.x;
    int t = threadIdx.x;  // 0..127

    float4 v = ((const float4*)(feats + row * DIM))[t];
    float ss = v.x * v.x + v.y * v.y + v.z * v.z + v.w * v.w;
#pragma unroll
    for (int o = 16; o > 0; o >>= 1) ss += __shfl_xor_sync(0xffffffffu, ss, o);

    __shared__ float sred[4];
    if ((t & 31) == 0) sred[t >> 5] = ss;
    __syncthreads();
    float tot = sred[0] + sred[1] + sred[2] + sred[3];
    float inv = 1.0f / sqrtf(tot);

    float4 o4 = make_float4(v.x * inv, v.y * inv, v.z * inv, v.w * inv);
    ((float4*)(g_normf + row * DIM))[t] = o4;

    if (t < NCLS) {
        if (labels[row * NCLS + t] > 0.5f) g_cls[row] = t;
    }
    if (t == 0) { g_pos[row] = 0.0f; g_all[row] = 0.0f; }
}

// ---------------------------------------------------------------------------
// Kernel 2: fused Gram-matrix tile + exp + masked row sums
// grid (BATCH/BN, BATCH/BM), 256 threads, 8x8 per thread (as 8 rows x 4 pairs)
// ---------------------------------------------------------------------------
__global__ void __launch_bounds__(256, 2)
contrastive_gemm_kernel() {
    __shared__ float As[BK][BM + SPAD];
    __shared__ float Bs[BK][BN + SPAD];
    __shared__ int clsA[BM];
    __shared__ int clsB[BN];

    const int tid = threadIdx.x;
    const int tx = tid & 15;       // 0..15, column group
    const int ty = tid >> 4;       // 0..15, row group
    const int rowBase = blockIdx.y * BM;
    const int colBase = blockIdx.x * BN;

    if (tid < BM) clsA[tid] = g_cls[rowBase + tid];
    else          clsB[tid - BM] = g_cls[colBase + (tid - BM)];

    unsigned long long acc[8][4];
#pragma unroll
    for (int i = 0; i < 8; i++)
#pragma unroll
        for (int p = 0; p < 4; p++) acc[i][p] = 0ull;

    for (int k0 = 0; k0 < DIM; k0 += BK) {
        // cooperative load: 128 rows x 16 k -> k-major smem tiles (transposed)
#pragma unroll
        for (int it = 0; it < 2; it++) {
            int s = tid + it * 256;        // 0..511 float4 slots
            int r = s >> 2;
            int c4 = s & 3;
            float4 va = *(const float4*)(g_normf + (rowBase + r) * DIM + k0 + c4 * 4);
            As[c4 * 4 + 0][r] = va.x;
            As[c4 * 4 + 1][r] = va.y;
            As[c4 * 4 + 2][r] = va.z;
            As[c4 * 4 + 3][r] = va.w;
            float4 vb = *(const float4*)(g_normf + (colBase + r) * DIM + k0 + c4 * 4);
            Bs[c4 * 4 + 0][r] = vb.x;
            Bs[c4 * 4 + 1][r] = vb.y;
            Bs[c4 * 4 + 2][r] = vb.z;
            Bs[c4 * 4 + 3][r] = vb.w;
        }
        __syncthreads();

#pragma unroll
        for (int kk = 0; kk < BK; kk++) {
            float a[8], b[8];
            *(float4*)(a)     = *(const float4*)&As[kk][ty * 8];
            *(float4*)(a + 4) = *(const float4*)&As[kk][ty * 8 + 4];
            *(float4*)(b)     = *(const float4*)&Bs[kk][tx * 8];
            *(float4*)(b + 4) = *(const float4*)&Bs[kk][tx * 8 + 4];

            unsigned long long bp[4], ad[8];
#pragma unroll
            for (int p = 0; p < 4; p++) bp[p] = pack2(b[2 * p], b[2 * p + 1]);
#pragma unroll
            for (int i = 0; i < 8; i++) ad[i] = pack2(a[i], a[i]);

#pragma unroll
            for (int i = 0; i < 8; i++)
#pragma unroll
                for (int p = 0; p < 4; p++) fma2(acc[i][p], ad[i], bp[p]);
        }
        __syncthreads();
    }

    // Epilogue: scale -> clip -> exp2 -> masked sums, reduce over tx, atomic
    const float SCL  = 1.44269504088896f / 0.07f;  // log2(e)/T : exp(x)=exp2(x*SCL')
    const float CLIP = 20.0f * 1.44269504088896f;  // clip(+-20) in log2 domain

    int cB[8];
#pragma unroll
    for (int j = 0; j < 8; j++) cB[j] = clsB[tx * 8 + j];

#pragma unroll
    for (int i = 0; i < 8; i++) {
        int gr = rowBase + ty * 8 + i;
        int myc = clsA[ty * 8 + i];
        float sum_all = 0.0f, sum_pos = 0.0f;
#pragma unroll
        for (int j = 0; j < 8; j++) {
            float lo, hi;
            unpack2(acc[i][j >> 1], lo, hi);
            float d = (j & 1) ? hi : lo;
            int gc = colBase + tx * 8 + j;
            float s = d * SCL;
            s = fminf(fmaxf(s, -CLIP), CLIP);
            float e = exp2f(s);
            if (gr == gc) e = 0.0f;   // diag: exp(-inf) = 0
            sum_all += e;
            if (myc == cB[j]) sum_pos += e;
        }
        // reduce across the 16 tx lanes (contiguous half-warp: xor 8,4,2,1 stays inside)
#pragma unroll
        for (int o = 8; o > 0; o >>= 1) {
            sum_all += __shfl_xor_sync(0xffffffffu, sum_all, o);
            sum_pos += __shfl_xor_sync(0xffffffffu, sum_pos, o);
        }
        if (tx == 0) {
            atomicAdd(&g_all[gr], sum_all);
            atomicAdd(&g_pos[gr], sum_pos);
        }
    }
}

// ---------------------------------------------------------------------------
// Kernel 3: per-row loss + validity + mean  (single block)
// ---------------------------------------------------------------------------
__global__ void finalize_kernel(float* __restrict__ out) {
    __shared__ int cnt[NCLS];
    __shared__ float s_tot[8];
    __shared__ float s_cnt[8];
    int t = threadIdx.x;  // 256

    if (t < NCLS) cnt[t] = 0;
    __syncthreads();
    for (int r = t; r < BATCH; r += 256) atomicAdd(&cnt[g_cls[r]], 1);
    __syncthreads();

    float total = 0.0f, nval = 0.0f;
    for (int r = t; r < BATCH; r += 256) {
        int c = g_cls[r];
        if (cnt[c] >= 2) {  // row has at least one positive
            float pos = g_pos[r];
            float all = g_all[r];
            float li = -logf(pos / (all + 1e-8f) + 1e-8f);
            total += li;
            nval += 1.0f;
        }
    }
#pragma unroll
    for (int o = 16; o > 0; o >>= 1) {
        total += __shfl_xor_sync(0xffffffffu, total, o);
        nval  += __shfl_xor_sync(0xffffffffu, nval, o);
    }
    if ((t & 31) == 0) { s_tot[t >> 5] = total; s_cnt[t >> 5] = nval; }
    __syncthreads();
    if (t == 0) {
        float tt = 0.0f, nn = 0.0f;
#pragma unroll
        for (int w = 0; w < 8; w++) { tt += s_tot[w]; nn += s_cnt[w]; }
        out[0] = (nn > 0.0f) ? tt / nn : 0.0f;
    }
}

// ---------------------------------------------------------------------------
extern "C" void kernel_launch(void* const* d_in, const int* in_sizes, int n_in,
                              void* d_out, int out_size) {
    const float* features = (const float*)d_in[0];  // [4096, 512] f32
    const float* labels   = (const float*)d_in[1];  // [4096, 10]  f32
    float* out = (float*)d_out;

    normalize_kernel<<<BATCH, 128>>>(features, labels);
    dim3 grid(BATCH / BN, BATCH / BM);
    contrastive_gemm_kernel<<<grid, 256>>>();
    finalize_kernel<<<1, 256>>>(out);
}

// round 2
// speedup vs baseline: 1.6603x; 1.6603x over previous
#include <cuda_runtime.h>
#include <math.h>

#define BATCH 4096
#define DIM   512
#define NCLS  10

#define BM 128
#define BN 128
#define BK 16
#define SPAD 4   // smem row padding (floats)
#define NBLK (BATCH / BM)            // 32
#define NTRI (NBLK * (NBLK + 1) / 2) // 528 upper-triangular tiles

// Scratch (device globals -- no allocation allowed)
__device__ float g_normf[BATCH * DIM];   // normalized features, 8 MB
__device__ int   g_cls[BATCH];
__device__ float g_pos[BATCH];
__device__ float g_all[BATCH];

// ---------------------------------------------------------------------------
// packed f32x2 helpers (FFMA2 path: ptxas never emits it from C++, only PTX)
// ---------------------------------------------------------------------------
__device__ __forceinline__ unsigned long long pack2(float x, float y) {
    unsigned long long r;
    asm("mov.b64 %0, {%1, %2};"
        : "=l"(r) : "r"(__float_as_uint(x)), "r"(__float_as_uint(y)));
    return r;
}
__device__ __forceinline__ void fma2(unsigned long long& d,
                                     unsigned long long a,
                                     unsigned long long b) {
    asm("fma.rn.f32x2 %0, %1, %2, %0;" : "+l"(d) : "l"(a), "l"(b));
}
__device__ __forceinline__ void unpack2(unsigned long long v, float& lo, float& hi) {
    unsigned int a, b;
    asm("mov.b64 {%0, %1}, %2;" : "=r"(a), "=r"(b) : "l"(v));
    lo = __uint_as_float(a);
    hi = __uint_as_float(b);
}

// ---------------------------------------------------------------------------
// Kernel 1: L2-normalize rows, extract class id, zero accumulators
// ---------------------------------------------------------------------------
__global__ void normalize_kernel(const float* __restrict__ feats,
                                 const float* __restrict__ labels) {
    int row = blockIdx.x;
    int t = threadIdx.x;  // 0..127

    float4 v = ((const float4*)(feats + row * DIM))[t];
    float ss = v.x * v.x + v.y * v.y + v.z * v.z + v.w * v.w;
#pragma unroll
    for (int o = 16; o > 0; o >>= 1) ss += __shfl_xor_sync(0xffffffffu, ss, o);

    __shared__ float sred[4];
    if ((t & 31) == 0) sred[t >> 5] = ss;
    __syncthreads();
    float tot = sred[0] + sred[1] + sred[2] + sred[3];
    float inv = 1.0f / sqrtf(tot);

    float4 o4 = make_float4(v.x * inv, v.y * inv, v.z * inv, v.w * inv);
    ((float4*)(g_normf + row * DIM))[t] = o4;

    if (t < NCLS) {
        if (labels[row * NCLS + t] > 0.5f) g_cls[row] = t;
    }
    if (t == 0) { g_pos[row] = 0.0f; g_all[row] = 0.0f; }
}

// ---------------------------------------------------------------------------
// Kernel 2: SYMMETRIC fused Gram tile + exp + masked row AND column sums.
// Only upper-triangular tiles (bx >= by). Off-diagonal tiles contribute
// row-sums to the A-tile rows and column-sums to the B-tile rows (symmetry).
// ---------------------------------------------------------------------------
__global__ void __launch_bounds__(256, 2)
contrastive_gemm_kernel() {
    __shared__ float As[BK][BM + SPAD];
    __shared__ float Bs[BK][BN + SPAD];
    __shared__ int clsA[BM];
    __shared__ int clsB[BN];
    __shared__ float sColAll[8][BN];   // per-warp column partials
    __shared__ float sColPos[8][BN];

    // map linear block index -> upper-triangular (by, bx), bx >= by
    int rem = blockIdx.x;
    int by = 0;
    while (rem >= (NBLK - by)) { rem -= (NBLK - by); by++; }
    const int bx = by + rem;
    const bool isDiag = (bx == by);

    const int tid = threadIdx.x;
    const int tx = tid & 15;       // 0..15, column group
    const int ty = tid >> 4;       // 0..15, row group
    const int warp = tid >> 5;     // 0..7
    const int rowBase = by * BM;
    const int colBase = bx * BN;

    if (tid < BM) clsA[tid] = g_cls[rowBase + tid];
    else          clsB[tid - BM] = g_cls[colBase + (tid - BM)];

    unsigned long long acc[8][4];
#pragma unroll
    for (int i = 0; i < 8; i++)
#pragma unroll
        for (int p = 0; p < 4; p++) acc[i][p] = 0ull;

    for (int k0 = 0; k0 < DIM; k0 += BK) {
        // cooperative load: 128 rows x 16 k -> k-major smem tiles (transposed)
#pragma unroll
        for (int it = 0; it < 2; it++) {
            int s = tid + it * 256;        // 0..511 float4 slots
            int r = s >> 2;
            int c4 = s & 3;
            float4 va = *(const float4*)(g_normf + (rowBase + r) * DIM + k0 + c4 * 4);
            As[c4 * 4 + 0][r] = va.x;
            As[c4 * 4 + 1][r] = va.y;
            As[c4 * 4 + 2][r] = va.z;
            As[c4 * 4 + 3][r] = va.w;
            float4 vb = *(const float4*)(g_normf + (colBase + r) * DIM + k0 + c4 * 4);
            Bs[c4 * 4 + 0][r] = vb.x;
            Bs[c4 * 4 + 1][r] = vb.y;
            Bs[c4 * 4 + 2][r] = vb.z;
            Bs[c4 * 4 + 3][r] = vb.w;
        }
        __syncthreads();

#pragma unroll
        for (int kk = 0; kk < BK; kk++) {
            float a[8], b[8];
            *(float4*)(a)     = *(const float4*)&As[kk][ty * 8];
            *(float4*)(a + 4) = *(const float4*)&As[kk][ty * 8 + 4];
            *(float4*)(b)     = *(const float4*)&Bs[kk][tx * 8];
            *(float4*)(b + 4) = *(const float4*)&Bs[kk][tx * 8 + 4];

            unsigned long long bp[4], ad[8];
#pragma unroll
            for (int p = 0; p < 4; p++) bp[p] = pack2(b[2 * p], b[2 * p + 1]);
#pragma unroll
            for (int i = 0; i < 8; i++) ad[i] = pack2(a[i], a[i]);

#pragma unroll
            for (int i = 0; i < 8; i++)
#pragma unroll
                for (int p = 0; p < 4; p++) fma2(acc[i][p], ad[i], bp[p]);
        }
        __syncthreads();
    }

    // Epilogue: scale -> clip -> exp2 -> masked sums (rows + columns)
    const float SCL  = 1.44269504088896f / 0.07f;  // exp(x/T) = exp2(x*SCL)
    const float CLIP = 20.0f * 1.44269504088896f;  // clip(+-20) in log2 domain

    int cB[8];
#pragma unroll
    for (int j = 0; j < 8; j++) cB[j] = clsB[tx * 8 + j];

    float cAll[8], cPos[8];
#pragma unroll
    for (int j = 0; j < 8; j++) { cAll[j] = 0.0f; cPos[j] = 0.0f; }

#pragma unroll
    for (int i = 0; i < 8; i++) {
        int gr = rowBase + ty * 8 + i;
        int myc = clsA[ty * 8 + i];
        float sum_all = 0.0f, sum_pos = 0.0f;
#pragma unroll
        for (int j = 0; j < 8; j++) {
            float lo, hi;
            unpack2(acc[i][j >> 1], lo, hi);
            float d = (j & 1) ? hi : lo;
            int gc = colBase + tx * 8 + j;
            float s = d * SCL;
            s = fminf(fmaxf(s, -CLIP), CLIP);
            float e = exp2f(s);
            if (isDiag && gr == gc) e = 0.0f;   // diag: exp(-inf) = 0
            bool same = (myc == cB[j]);
            sum_all += e;
            if (same) sum_pos += e;
            if (!isDiag) {               // symmetric contribution to column rows
                cAll[j] += e;
                if (same) cPos[j] += e;
            }
        }
        // reduce across the 16 tx lanes (xor 8,4,2,1 stays inside half-warp)
#pragma unroll
        for (int o = 8; o > 0; o >>= 1) {
            sum_all += __shfl_xor_sync(0xffffffffu, sum_all, o);
            sum_pos += __shfl_xor_sync(0xffffffffu, sum_pos, o);
        }
        if (tx == 0) {
            atomicAdd(&g_all[gr], sum_all);
            atomicAdd(&g_pos[gr], sum_pos);
        }
    }

    if (!isDiag) {
        // combine the ty-pair within each warp (lane ^ 16 has same tx)
#pragma unroll
        for (int j = 0; j < 8; j++) {
            cAll[j] += __shfl_xor_sync(0xffffffffu, cAll[j], 16);
            cPos[j] += __shfl_xor_sync(0xffffffffu, cPos[j], 16);
        }
        if ((tid & 31) < 16) {   // lanes 0..15 of each warp write
#pragma unroll
            for (int j = 0; j < 8; j++) {
                sColAll[warp][tx * 8 + j] = cAll[j];
                sColPos[warp][tx * 8 + j] = cPos[j];
            }
        }
        __syncthreads();
        // 256 threads: first 128 reduce "all", next 128 reduce "pos"
        if (tid < BN) {
            float s = 0.0f;
#pragma unroll
            for (int w = 0; w < 8; w++) s += sColAll[w][tid];
            atomicAdd(&g_all[colBase + tid], s);
        } else {
            int c = tid - BN;
            float s = 0.0f;
#pragma unroll
            for (int w = 0; w < 8; w++) s += sColPos[w][c];
            atomicAdd(&g_pos[colBase + c], s);
        }
    }
}

// ---------------------------------------------------------------------------
// Kernel 3: per-row loss + validity + mean  (single block)
// ---------------------------------------------------------------------------
__global__ void finalize_kernel(float* __restrict__ out) {
    __shared__ int cnt[NCLS];
    __shared__ float s_tot[8];
    __shared__ float s_cnt[8];
    int t = threadIdx.x;  // 256

    if (t < NCLS) cnt[t] = 0;
    __syncthreads();
    for (int r = t; r < BATCH; r += 256) atomicAdd(&cnt[g_cls[r]], 1);
    __syncthreads();

    float total = 0.0f, nval = 0.0f;
    for (int r = t; r < BATCH; r += 256) {
        int c = g_cls[r];
        if (cnt[c] >= 2) {  // row has at least one positive
            float pos = g_pos[r];
            float all = g_all[r];
            float li = -logf(pos / (all + 1e-8f) + 1e-8f);
            total += li;
            nval += 1.0f;
        }
    }
#pragma unroll
    for (int o = 16; o > 0; o >>= 1) {
        total += __shfl_xor_sync(0xffffffffu, total, o);
        nval  += __shfl_xor_sync(0xffffffffu, nval, o);
    }
    if ((t & 31) == 0) { s_tot[t >> 5] = total; s_cnt[t >> 5] = nval; }
    __syncthreads();
    if (t == 0) {
        float tt = 0.0f, nn = 0.0f;
#pragma unroll
        for (int w = 0; w < 8; w++) { tt += s_tot[w]; nn += s_cnt[w]; }
        out[0] = (nn > 0.0f) ? tt / nn : 0.0f;
    }
}

// ---------------------------------------------------------------------------
extern "C" void kernel_launch(void* const* d_in, const int* in_sizes, int n_in,
                              void* d_out, int out_size) {
    const float* features = (const float*)d_in[0];  // [4096, 512] f32
    const float* labels   = (const float*)d_in[1];  // [4096, 10]  f32
    float* out = (float*)d_out;

    normalize_kernel<<<BATCH, 128>>>(features, labels);
    contrastive_gemm_kernel<<<NTRI, 256>>>();
    finalize_kernel<<<1, 256>>>(out);
}

// round 4
// speedup vs baseline: 4.6734x; 2.8149x over previous
#include <cuda_runtime.h>
#include <math.h>
#include <stdint.h>

#define BATCH 4096
#define DIM   512
#define NCLS  10

#define BM 128
#define NBLK (BATCH / BM)            // 32
#define NTRI (NBLK * (NBLK + 1) / 2) // 528 upper-triangular tiles

#define NCHUNK 16                    // K chunks of 32 floats
#define KCHUNK 32

#define STRIDE 36                            // floats per smem tile row (bank-spread)
#define TILE_BYTES (128 * STRIDE * 4)        // 18432
#define ABUF(b) ((b) * 2 * TILE_BYTES)
#define BBUF(b) ((b) * 2 * TILE_BYTES + TILE_BYTES)
#define SMEM_DYN (4 * TILE_BYTES)            // 73728 bytes

// Scratch (device globals -- no allocation allowed)
__device__ float g_normf[BATCH * DIM];   // tf32-rounded normalized features
__device__ int   g_cls[BATCH];
__device__ float g_pos[BATCH];
__device__ float g_all[BATCH];

// ---------------------------------------------------------------------------
__device__ __forceinline__ uint32_t smem_u32(const void* p) {
    uint32_t a;
    asm("{ .reg .u64 t; cvta.to.shared.u64 t, %1; cvt.u32.u64 %0, t; }"
        : "=r"(a) : "l"(p));
    return a;
}

__device__ __forceinline__ void mma_tf32(float* c, const uint32_t* a,
                                         const uint32_t* b) {
    asm volatile(
        "mma.sync.aligned.m16n8k8.row.col.f32.tf32.tf32.f32 "
        "{%0,%1,%2,%3}, {%4,%5,%6,%7}, {%8,%9}, {%0,%1,%2,%3};"
        : "+f"(c[0]), "+f"(c[1]), "+f"(c[2]), "+f"(c[3])
        : "r"(a[0]), "r"(a[1]), "r"(a[2]), "r"(a[3]), "r"(b[0]), "r"(b[1]));
}

__device__ __forceinline__ float fast_exp2(float x) {
    float r;
    asm("ex2.approx.ftz.f32 %0, %1;" : "=f"(r) : "f"(x));
    return r;
}

// ---------------------------------------------------------------------------
// Kernel 1: normalize + round-to-tf32, extract class id, zero accumulators
// ---------------------------------------------------------------------------
__global__ void normalize_kernel(const float* __restrict__ feats,
                                 const float* __restrict__ labels) {
    int row = blockIdx.x;
    int t = threadIdx.x;  // 0..127

    float4 v = ((const float4*)(feats + row * DIM))[t];
    float ss = v.x * v.x + v.y * v.y + v.z * v.z + v.w * v.w;
#pragma unroll
    for (int o = 16; o > 0; o >>= 1) ss += __shfl_xor_sync(0xffffffffu, ss, o);

    __shared__ float sred[4];
    if ((t & 31) == 0) sred[t >> 5] = ss;
    __syncthreads();
    float tot = sred[0] + sred[1] + sred[2] + sred[3];
    float inv = 1.0f / sqrtf(tot);

    float o0 = v.x * inv, o1 = v.y * inv, o2 = v.z * inv, o3 = v.w * inv;
    uint32_t u0, u1, u2, u3;
    asm("cvt.rna.tf32.f32 %0, %1;" : "=r"(u0) : "f"(o0));
    asm("cvt.rna.tf32.f32 %0, %1;" : "=r"(u1) : "f"(o1));
    asm("cvt.rna.tf32.f32 %0, %1;" : "=r"(u2) : "f"(o2));
    asm("cvt.rna.tf32.f32 %0, %1;" : "=r"(u3) : "f"(o3));
    float4 o4 = make_float4(__uint_as_float(u0), __uint_as_float(u1),
                            __uint_as_float(u2), __uint_as_float(u3));
    ((float4*)(g_normf + row * DIM))[t] = o4;

    if (t < NCLS) {
        if (labels[row * NCLS + t] > 0.5f) g_cls[row] = t;
    }
    if (t == 0) { g_pos[row] = 0.0f; g_all[row] = 0.0f; }
}

// ---------------------------------------------------------------------------
// Kernel 2: mma.sync tf32 symmetric Gram tile + exp + register-only epilogue
// 256 threads = 8 warps in a 2x4 grid; warp tile 64x32; thread owns 8r x 8c.
// ---------------------------------------------------------------------------
__global__ void __launch_bounds__(256, 2)
contrastive_mma_kernel() {
    extern __shared__ char smem[];
    __shared__ int clsA_s[128];
    __shared__ int clsB_s[128];
    const uint32_t sb = smem_u32(smem);

    const int tid = threadIdx.x;
    const int lane = tid & 31;
    const int wid = tid >> 5;
    const int wr = wid >> 2;        // 0..1 warp row
    const int wc = wid & 3;         // 0..3 warp col
    const int g = lane >> 2;        // 0..7 group
    const int tig = lane & 3;       // 0..3 thread-in-group

    // map linear block index -> upper-triangular (by, bx), bx >= by
    int rem = blockIdx.x;
    int by = 0;
    while (rem >= (NBLK - by)) { rem -= (NBLK - by); by++; }
    const int bx = by + rem;
    const bool isDiag = (bx == by);
    const int rowBase = by * BM;
    const int colBase = bx * BM;

    if (tid < 128) clsA_s[tid] = g_cls[rowBase + tid];
    else           clsB_s[tid - 128] = g_cls[colBase + (tid - 128)];

    float acc[4][4][4];
#pragma unroll
    for (int mi = 0; mi < 4; mi++)
#pragma unroll
        for (int ni = 0; ni < 4; ni++)
#pragma unroll
            for (int r = 0; r < 4; r++) acc[mi][ni][r] = 0.0f;

    // ---- async loader: one K-chunk (128 rows x 32 floats) for A and B ----
    auto load_chunk = [&](int c, int buf) {
        const int k0 = c * KCHUNK;
#pragma unroll
        for (int it = 0; it < 8; it++) {
            int flat = it * 256 + tid;      // 0..2047 16B segments
            int tile = flat >> 10;          // 0 = A, 1 = B
            int r = (flat >> 3) & 127;
            int seg = flat & 7;
            const float* src = g_normf
                + (size_t)((tile ? colBase : rowBase) + r) * DIM + k0 + seg * 4;
            uint32_t dst = sb + (tile ? BBUF(buf) : ABUF(buf))
                         + r * (STRIDE * 4) + seg * 16;
            asm volatile("cp.async.cg.shared.global [%0], [%1], 16;"
                         :: "r"(dst), "l"(src) : "memory");
        }
        asm volatile("cp.async.commit_group;" ::: "memory");
    };

    auto compute_chunk = [&](int buf) {
        const float* As = (const float*)(smem + ABUF(buf));
        const float* Bs = (const float*)(smem + BBUF(buf));
#pragma unroll
        for (int ks = 0; ks < 4; ks++) {
            const int kk = ks * 8;
            uint32_t a[4][4], b[4][2];
#pragma unroll
            for (int mi = 0; mi < 4; mi++) {
                int rowA = wr * 64 + mi * 16 + g;
                a[mi][0] = __float_as_uint(As[rowA * STRIDE + kk + tig]);
                a[mi][1] = __float_as_uint(As[(rowA + 8) * STRIDE + kk + tig]);
                a[mi][2] = __float_as_uint(As[rowA * STRIDE + kk + tig + 4]);
                a[mi][3] = __float_as_uint(As[(rowA + 8) * STRIDE + kk + tig + 4]);
            }
#pragma unroll
            for (int ni = 0; ni < 4; ni++) {
                int colB = wc * 32 + ni * 8 + g;
                b[ni][0] = __float_as_uint(Bs[colB * STRIDE + kk + tig]);
                b[ni][1] = __float_as_uint(Bs[colB * STRIDE + kk + tig + 4]);
            }
#pragma unroll
            for (int mi = 0; mi < 4; mi++)
#pragma unroll
                for (int ni = 0; ni < 4; ni++)
                    mma_tf32(acc[mi][ni], a[mi], b[ni]);
        }
    };

    // ---- double-buffered mainloop ----
    load_chunk(0, 0);
    for (int c = 0; c < NCHUNK; c++) {
        if (c < NCHUNK - 1) {
            load_chunk(c + 1, (c + 1) & 1);
            asm volatile("cp.async.wait_group 1;" ::: "memory");
        } else {
            asm volatile("cp.async.wait_group 0;" ::: "memory");
        }
        __syncthreads();
        compute_chunk(c & 1);
        __syncthreads();
    }

    // ---- register-only epilogue ----
    const float SCL  = 1.44269504088896f / 0.07f;   // exp(x/T) = exp2(x*SCL)
    const float CLIP = 20.0f * 1.44269504088896f;   // +-20 in log2 domain

    int rcls[4][2], ccls[4][2];
#pragma unroll
    for (int mi = 0; mi < 4; mi++)
#pragma unroll
        for (int h = 0; h < 2; h++)
            rcls[mi][h] = clsA_s[wr * 64 + mi * 16 + h * 8 + g];
#pragma unroll
    for (int ni = 0; ni < 4; ni++)
#pragma unroll
        for (int q = 0; q < 2; q++)
            ccls[ni][q] = clsB_s[wc * 32 + ni * 8 + tig * 2 + q];

    float rAll[4][2], rPos[4][2], cAll[4][2], cPos[4][2];
#pragma unroll
    for (int i = 0; i < 4; i++)
#pragma unroll
        for (int h = 0; h < 2; h++) {
            rAll[i][h] = 0.0f; rPos[i][h] = 0.0f;
            cAll[i][h] = 0.0f; cPos[i][h] = 0.0f;
        }

#pragma unroll
    for (int mi = 0; mi < 4; mi++)
#pragma unroll
        for (int ni = 0; ni < 4; ni++)
#pragma unroll
            for (int h = 0; h < 2; h++)
#pragma unroll
                for (int q = 0; q < 2; q++) {
                    float v = acc[mi][ni][h * 2 + q];
                    float s = fminf(fmaxf(v * SCL, -CLIP), CLIP);
                    float e = fast_exp2(s);
                    if (isDiag) {
                        int rl = wr * 64 + mi * 16 + h * 8 + g;
                        int cl = wc * 32 + ni * 8 + tig * 2 + q;
                        if (rl == cl) e = 0.0f;
                    }
                    rAll[mi][h] += e;
                    cAll[ni][q] += e;
                    if (rcls[mi][h] == ccls[ni][q]) {
                        rPos[mi][h] += e;
                        cPos[ni][q] += e;
                    }
                }

    // row sums: reduce over tig (lane bits 0,1)
#pragma unroll
    for (int mi = 0; mi < 4; mi++)
#pragma unroll
        for (int h = 0; h < 2; h++) {
#pragma unroll
            for (int o = 1; o < 4; o <<= 1) {
                rAll[mi][h] += __shfl_xor_sync(0xffffffffu, rAll[mi][h], o);
                rPos[mi][h] += __shfl_xor_sync(0xffffffffu, rPos[mi][h], o);
            }
        }
    if (tig == 0) {
#pragma unroll
        for (int mi = 0; mi < 4; mi++)
#pragma unroll
            for (int h = 0; h < 2; h++) {
                int gr = rowBase + wr * 64 + mi * 16 + h * 8 + g;
                atomicAdd(&g_all[gr], rAll[mi][h]);
                atomicAdd(&g_pos[gr], rPos[mi][h]);
            }
    }

    // symmetric column sums (off-diagonal only): reduce over g (lane bits 2..4)
    if (!isDiag) {
#pragma unroll
        for (int ni = 0; ni < 4; ni++)
#pragma unroll
            for (int q = 0; q < 2; q++) {
#pragma unroll
                for (int o = 4; o < 32; o <<= 1) {
                    cAll[ni][q] += __shfl_xor_sync(0xffffffffu, cAll[ni][q], o);
                    cPos[ni][q] += __shfl_xor_sync(0xffffffffu, cPos[ni][q], o);
                }
            }
        if (g == 0) {
#pragma unroll
            for (int ni = 0; ni < 4; ni++)
#pragma unroll
                for (int q = 0; q < 2; q++) {
                    int gc = colBase + wc * 32 + ni * 8 + tig * 2 + q;
                    atomicAdd(&g_all[gc], cAll[ni][q]);
                    atomicAdd(&g_pos[gc], cPos[ni][q]);
                }
        }
    }
}

// ---------------------------------------------------------------------------
// Kernel 3: per-row loss + validity + mean  (single block)
// ---------------------------------------------------------------------------
__global__ void finalize_kernel(float* __restrict__ out) {
    __shared__ int cnt[NCLS];
    __shared__ float s_tot[8];
    __shared__ float s_cnt[8];
    int t = threadIdx.x;  // 256

    if (t < NCLS) cnt[t] = 0;
    __syncthreads();
    for (int r = t; r < BATCH; r += 256) atomicAdd(&cnt[g_cls[r]], 1);
    __syncthreads();

    float total = 0.0f, nval = 0.0f;
    for (int r = t; r < BATCH; r += 256) {
        int c = g_cls[r];
        if (cnt[c] >= 2) {
            float pos = g_pos[r];
            float all = g_all[r];
            float li = -logf(pos / (all + 1e-8f) + 1e-8f);
            total += li;
            nval += 1.0f;
        }
    }
#pragma unroll
    for (int o = 16; o > 0; o >>= 1) {
        total += __shfl_xor_sync(0xffffffffu, total, o);
        nval  += __shfl_xor_sync(0xffffffffu, nval, o);
    }
    if ((t & 31) == 0) { s_tot[t >> 5] = total; s_cnt[t >> 5] = nval; }
    __syncthreads();
    if (t == 0) {
        float tt = 0.0f, nn = 0.0f;
#pragma unroll
        for (int w = 0; w < 8; w++) { tt += s_tot[w]; nn += s_cnt[w]; }
        out[0] = (nn > 0.0f) ? tt / nn : 0.0f;
    }
}

// ---------------------------------------------------------------------------
extern "C" void kernel_launch(void* const* d_in, const int* in_sizes, int n_in,
                              void* d_out, int out_size) {
    const float* features = (const float*)d_in[0];  // [4096, 512] f32
    const float* labels   = (const float*)d_in[1];  // [4096, 10]  f32
    float* out = (float*)d_out;

    cudaFuncSetAttribute(contrastive_mma_kernel,
                         cudaFuncAttributeMaxDynamicSharedMemorySize, SMEM_DYN);

    normalize_kernel<<<BATCH, 128>>>(features, labels);
    contrastive_mma_kernel<<<NTRI, 256, SMEM_DYN>>>();
    finalize_kernel<<<1, 256>>>(out);
}

// round 5
// speedup vs baseline: 6.9278x; 1.4824x over previous
#include <cuda_runtime.h>
#include <cuda_fp16.h>
#include <math.h>
#include <stdint.h>

#define BATCH 4096
#define DIM   512
#define NCLS  10

#define BM 128
#define NBLK (BATCH / BM)            // 32
#define NTRI (NBLK * (NBLK + 1) / 2) // 528 upper-triangular tiles

#define NCHUNK 16                    // K chunks of 32 halves
#define KCHUNK 32

#define RSTRIDE 80                           // bytes per smem tile row (32 fp16 + pad)
#define TILE_BYTES (128 * RSTRIDE)           // 10240
#define ABUF(b) ((b) * 2 * TILE_BYTES)
#define BBUF(b) ((b) * 2 * TILE_BYTES + TILE_BYTES)
#define SMEM_DYN (4 * TILE_BYTES)            // 40960 bytes

// Scratch (device globals -- no allocation allowed)
__device__ __half g_normh[BATCH * DIM];  // fp16 normalized features (4 MB)
__device__ int    g_cls[BATCH];
__device__ float  g_pos[BATCH];
__device__ float  g_all[BATCH];

// ---------------------------------------------------------------------------
__device__ __forceinline__ uint32_t smem_u32(const void* p) {
    uint32_t a;
    asm("{ .reg .u64 t; cvta.to.shared.u64 t, %1; cvt.u32.u64 %0, t; }"
        : "=r"(a) : "l"(p));
    return a;
}

#define LDSM_X4(d, addr) \
    asm volatile("ldmatrix.sync.aligned.m8n8.x4.shared.b16 {%0,%1,%2,%3}, [%4];" \
                 : "=r"((d)[0]), "=r"((d)[1]), "=r"((d)[2]), "=r"((d)[3]) \
                 : "r"(addr))

__device__ __forceinline__ void mma_f16(float* c, const uint32_t* a,
                                        uint32_t b0, uint32_t b1) {
    asm volatile(
        "mma.sync.aligned.m16n8k16.row.col.f32.f16.f16.f32 "
        "{%0,%1,%2,%3}, {%4,%5,%6,%7}, {%8,%9}, {%0,%1,%2,%3};"
        : "+f"(c[0]), "+f"(c[1]), "+f"(c[2]), "+f"(c[3])
        : "r"(a[0]), "r"(a[1]), "r"(a[2]), "r"(a[3]), "r"(b0), "r"(b1));
}

__device__ __forceinline__ float fast_exp2(float x) {
    float r;
    asm("ex2.approx.ftz.f32 %0, %1;" : "=f"(r) : "f"(x));
    return r;
}

__device__ __forceinline__ uint32_t pack_h2(float a, float b) {
    uint32_t r;
    asm("{ .reg .b16 l, h;\n\t"
        "cvt.rn.f16.f32 l, %1;\n\t"
        "cvt.rn.f16.f32 h, %2;\n\t"
        "mov.b32 %0, {l, h}; }" : "=r"(r) : "f"(a), "f"(b));
    return r;
}

// ---------------------------------------------------------------------------
// Kernel 1: L2-normalize -> fp16, class id, zero accumulators. Warp per row.
// ---------------------------------------------------------------------------
__global__ void __launch_bounds__(256)
normalize_kernel(const float* __restrict__ feats,
                 const float* __restrict__ labels) {
    const int wid = threadIdx.x >> 5;
    const int lane = threadIdx.x & 31;
    const int row = blockIdx.x * 8 + wid;

    float4 v[4];
    float ss = 0.0f;
#pragma unroll
    for (int k = 0; k < 4; k++) {
        v[k] = ((const float4*)(feats + row * DIM))[k * 32 + lane];
        ss += v[k].x * v[k].x + v[k].y * v[k].y + v[k].z * v[k].z + v[k].w * v[k].w;
    }
#pragma unroll
    for (int o = 16; o > 0; o >>= 1) ss += __shfl_xor_sync(0xffffffffu, ss, o);
    float inv = 1.0f / sqrtf(ss);

#pragma unroll
    for (int k = 0; k < 4; k++) {
        uint2 u;
        u.x = pack_h2(v[k].x * inv, v[k].y * inv);
        u.y = pack_h2(v[k].z * inv, v[k].w * inv);
        ((uint2*)(g_normh + row * DIM))[k * 32 + lane] = u;
    }

    if (lane < NCLS) {
        if (labels[row * NCLS + lane] > 0.5f) g_cls[row] = lane;
    }
    if (lane == 0) { g_pos[row] = 0.0f; g_all[row] = 0.0f; }
}

// ---------------------------------------------------------------------------
// Kernel 2: fp16 m16n8k16 symmetric Gram tile + exp + register epilogue.
// 8 warps (2x4); warp tile 64x32; thread owns 8 rows x 8 cols of fp32 acc.
// ---------------------------------------------------------------------------
__global__ void __launch_bounds__(256, 2)
contrastive_mma_kernel() {
    extern __shared__ char smem[];
    __shared__ int clsA_s[128];
    __shared__ int clsB_s[128];
    const uint32_t sb = smem_u32(smem);

    const int tid = threadIdx.x;
    const int lane = tid & 31;
    const int wid = tid >> 5;
    const int wr = wid >> 2;        // 0..1 warp row
    const int wc = wid & 3;         // 0..3 warp col
    const int g = lane >> 2;        // 0..7
    const int tig = lane & 3;       // 0..3

    // map linear block index -> upper-triangular (by, bx), bx >= by
    int rem = blockIdx.x;
    int by = 0;
    while (rem >= (NBLK - by)) { rem -= (NBLK - by); by++; }
    const int bx = by + rem;
    const bool isDiag = (bx == by);
    const int rowBase = by * BM;
    const int colBase = bx * BM;

    if (tid < 128) clsA_s[tid] = g_cls[rowBase + tid];
    else           clsB_s[tid - 128] = g_cls[colBase + (tid - 128)];

    // per-lane ldmatrix offsets (bytes within tile)
    const int mA = lane >> 3;       // matrix index 0..3
    const int rA = lane & 7;
    const uint32_t aOff = (uint32_t)((wr * 64 + (mA & 1) * 8 + rA) * RSTRIDE
                                     + (mA >> 1) * 16);
    const uint32_t bOff = (uint32_t)((wc * 32 + (mA >> 1) * 8 + rA) * RSTRIDE
                                     + (mA & 1) * 16);

    float acc[4][4][4];
#pragma unroll
    for (int mi = 0; mi < 4; mi++)
#pragma unroll
        for (int ni = 0; ni < 4; ni++)
#pragma unroll
            for (int r = 0; r < 4; r++) acc[mi][ni][r] = 0.0f;

    auto load_chunk = [&](int c, int buf) {
        const int k0 = c * KCHUNK;
#pragma unroll
        for (int it = 0; it < 4; it++) {
            int flat = it * 256 + tid;      // 0..1023 16B segments
            int tile = flat >> 9;           // 0 = A, 1 = B
            int r = (flat >> 2) & 127;
            int seg = flat & 3;
            const __half* src = g_normh
                + (size_t)((tile ? colBase : rowBase) + r) * DIM + k0 + seg * 8;
            uint32_t dst = sb + (tile ? BBUF(buf) : ABUF(buf))
                         + r * RSTRIDE + seg * 16;
            asm volatile("cp.async.cg.shared.global [%0], [%1], 16;"
                         :: "r"(dst), "l"(src) : "memory");
        }
        asm volatile("cp.async.commit_group;" ::: "memory");
    };

    auto compute_chunk = [&](int buf) {
        const uint32_t aBase = sb + ABUF(buf) + aOff;
        const uint32_t bBase = sb + BBUF(buf) + bOff;
#pragma unroll
        for (int ks = 0; ks < 2; ks++) {       // two k16 steps per 32-chunk
            uint32_t a[4][4], b[2][4];
#pragma unroll
            for (int mi = 0; mi < 4; mi++)
                LDSM_X4(a[mi], aBase + mi * (16 * RSTRIDE) + ks * 32);
#pragma unroll
            for (int p = 0; p < 2; p++)        // ni pair p covers ni=2p,2p+1
                LDSM_X4(b[p], bBase + p * (16 * RSTRIDE) + ks * 32);
#pragma unroll
            for (int mi = 0; mi < 4; mi++)
#pragma unroll
                for (int ni = 0; ni < 4; ni++)
                    mma_f16(acc[mi][ni], a[mi],
                            b[ni >> 1][2 * (ni & 1)], b[ni >> 1][2 * (ni & 1) + 1]);
        }
    };

    // ---- double-buffered mainloop ----
    load_chunk(0, 0);
    for (int c = 0; c < NCHUNK; c++) {
        if (c < NCHUNK - 1) {
            load_chunk(c + 1, (c + 1) & 1);
            asm volatile("cp.async.wait_group 1;" ::: "memory");
        } else {
            asm volatile("cp.async.wait_group 0;" ::: "memory");
        }
        __syncthreads();
        compute_chunk(c & 1);
        __syncthreads();
    }

    // ---- register-only epilogue ----
    const float SCL  = 1.44269504088896f / 0.07f;   // exp(x/T) = exp2(x*SCL)
    const float CLIP = 20.0f * 1.44269504088896f;

    int rcls[4][2], ccls[4][2];
#pragma unroll
    for (int mi = 0; mi < 4; mi++)
#pragma unroll
        for (int h = 0; h < 2; h++)
            rcls[mi][h] = clsA_s[wr * 64 + mi * 16 + h * 8 + g];
#pragma unroll
    for (int ni = 0; ni < 4; ni++)
#pragma unroll
        for (int q = 0; q < 2; q++)
            ccls[ni][q] = clsB_s[wc * 32 + ni * 8 + tig * 2 + q];

    float rAll[4][2], rPos[4][2], cAll[4][2], cPos[4][2];
#pragma unroll
    for (int i = 0; i < 4; i++)
#pragma unroll
        for (int h = 0; h < 2; h++) {
            rAll[i][h] = 0.0f; rPos[i][h] = 0.0f;
            cAll[i][h] = 0.0f; cPos[i][h] = 0.0f;
        }

#pragma unroll
    for (int mi = 0; mi < 4; mi++)
#pragma unroll
        for (int ni = 0; ni < 4; ni++)
#pragma unroll
            for (int h = 0; h < 2; h++)
#pragma unroll
                for (int q = 0; q < 2; q++) {
                    float v = acc[mi][ni][h * 2 + q];
                    float s = fminf(fmaxf(v * SCL, -CLIP), CLIP);
                    float e = fast_exp2(s);
                    if (isDiag) {
                        int rl = wr * 64 + mi * 16 + h * 8 + g;
                        int cl = wc * 32 + ni * 8 + tig * 2 + q;
                        if (rl == cl) e = 0.0f;
                    }
                    rAll[mi][h] += e;
                    cAll[ni][q] += e;
                    if (rcls[mi][h] == ccls[ni][q]) {
                        rPos[mi][h] += e;
                        cPos[ni][q] += e;
                    }
                }

    // row sums: reduce over tig (lane bits 0,1)
#pragma unroll
    for (int mi = 0; mi < 4; mi++)
#pragma unroll
        for (int h = 0; h < 2; h++) {
#pragma unroll
            for (int o = 1; o < 4; o <<= 1) {
                rAll[mi][h] += __shfl_xor_sync(0xffffffffu, rAll[mi][h], o);
                rPos[mi][h] += __shfl_xor_sync(0xffffffffu, rPos[mi][h], o);
            }
        }
    if (tig == 0) {
#pragma unroll
        for (int mi = 0; mi < 4; mi++)
#pragma unroll
            for (int h = 0; h < 2; h++) {
                int gr = rowBase + wr * 64 + mi * 16 + h * 8 + g;
                atomicAdd(&g_all[gr], rAll[mi][h]);
                atomicAdd(&g_pos[gr], rPos[mi][h]);
            }
    }

    // symmetric column sums (off-diagonal only): reduce over g (lane bits 2..4)
    if (!isDiag) {
#pragma unroll
        for (int ni = 0; ni < 4; ni++)
#pragma unroll
            for (int q = 0; q < 2; q++) {
#pragma unroll
                for (int o = 4; o < 32; o <<= 1) {
                    cAll[ni][q] += __shfl_xor_sync(0xffffffffu, cAll[ni][q], o);
                    cPos[ni][q] += __shfl_xor_sync(0xffffffffu, cPos[ni][q], o);
                }
            }
        if (g == 0) {
#pragma unroll
            for (int ni = 0; ni < 4; ni++)
#pragma unroll
                for (int q = 0; q < 2; q++) {
                    int gc = colBase + wc * 32 + ni * 8 + tig * 2 + q;
                    atomicAdd(&g_all[gc], cAll[ni][q]);
                    atomicAdd(&g_pos[gc], cPos[ni][q]);
                }
        }
    }
}

// ---------------------------------------------------------------------------
// Kernel 3: per-row loss + validity + mean  (single block)
// ---------------------------------------------------------------------------
__global__ void finalize_kernel(float* __restrict__ out) {
    __shared__ int cnt[NCLS];
    __shared__ float s_tot[8];
    __shared__ float s_cnt[8];
    int t = threadIdx.x;  // 256

    if (t < NCLS) cnt[t] = 0;
    __syncthreads();
    for (int r = t; r < BATCH; r += 256) atomicAdd(&cnt[g_cls[r]], 1);
    __syncthreads();

    float total = 0.0f, nval = 0.0f;
    for (int r = t; r < BATCH; r += 256) {
        int c = g_cls[r];
        if (cnt[c] >= 2) {
            float pos = g_pos[r];
            float all = g_all[r];
            float li = -logf(pos / (all + 1e-8f) + 1e-8f);
            total += li;
            nval += 1.0f;
        }
    }
#pragma unroll
    for (int o = 16; o > 0; o >>= 1) {
        total += __shfl_xor_sync(0xffffffffu, total, o);
        nval  += __shfl_xor_sync(0xffffffffu, nval, o);
    }
    if ((t & 31) == 0) { s_tot[t >> 5] = total; s_cnt[t >> 5] = nval; }
    __syncthreads();
    if (t == 0) {
        float tt = 0.0f, nn = 0.0f;
#pragma unroll
        for (int w = 0; w < 8; w++) { tt += s_tot[w]; nn += s_cnt[w]; }
        out[0] = (nn > 0.0f) ? tt / nn : 0.0f;
    }
}

// ---------------------------------------------------------------------------
extern "C" void kernel_launch(void* const* d_in, const int* in_sizes, int n_in,
                              void* d_out, int out_size) {
    const float* features = (const float*)d_in[0];  // [4096, 512] f32
    const float* labels   = (const float*)d_in[1];  // [4096, 10]  f32
    float* out = (float*)d_out;

    cudaFuncSetAttribute(contrastive_mma_kernel,
                         cudaFuncAttributeMaxDynamicSharedMemorySize, SMEM_DYN);

    normalize_kernel<<<BATCH / 8, 256>>>(features, labels);
    contrastive_mma_kernel<<<NTRI, 256, SMEM_DYN>>>();
    finalize_kernel<<<1, 256>>>(out);
}

// round 6
// speedup vs baseline: 8.4273x; 1.2164x over previous
#include <cuda_runtime.h>
#include <cuda_fp16.h>
#include <math.h>
#include <stdint.h>

#define BATCH 4096
#define DIM   512
#define NCLS  10

#define BM 128
#define NBLK (BATCH / BM)            // 32
#define NTRI (NBLK * (NBLK + 1) / 2) // 528 upper-triangular tiles

#define NCHUNK 16                    // K chunks of 32 halves
#define KCHUNK 32
#define NSTAGE 4

#define RSTRIDE 80                           // bytes per smem tile row (32 fp16 + pad)
#define TILE_BYTES (128 * RSTRIDE)           // 10240
#define ABUF(b) ((b) * 2 * TILE_BYTES)
#define BBUF(b) ((b) * 2 * TILE_BYTES + TILE_BYTES)
#define SMEM_DYN (NSTAGE * 2 * TILE_BYTES)   // 81920 bytes

// Scratch (device globals -- no allocation allowed)
__device__ __half g_normh[BATCH * DIM];  // fp16 normalized features (4 MB)
__device__ int    g_cls[BATCH];
__device__ float  g_pos[BATCH];
__device__ float  g_all[BATCH];

// ---------------------------------------------------------------------------
__device__ __forceinline__ uint32_t smem_u32(const void* p) {
    uint32_t a;
    asm("{ .reg .u64 t; cvta.to.shared.u64 t, %1; cvt.u32.u64 %0, t; }"
        : "=r"(a) : "l"(p));
    return a;
}

#define LDSM_X4(d, addr) \
    asm volatile("ldmatrix.sync.aligned.m8n8.x4.shared.b16 {%0,%1,%2,%3}, [%4];" \
                 : "=r"((d)[0]), "=r"((d)[1]), "=r"((d)[2]), "=r"((d)[3]) \
                 : "r"(addr))

__device__ __forceinline__ void mma_f16(float* c, const uint32_t* a,
                                        uint32_t b0, uint32_t b1) {
    asm volatile(
        "mma.sync.aligned.m16n8k16.row.col.f32.f16.f16.f32 "
        "{%0,%1,%2,%3}, {%4,%5,%6,%7}, {%8,%9}, {%0,%1,%2,%3};"
        : "+f"(c[0]), "+f"(c[1]), "+f"(c[2]), "+f"(c[3])
        : "r"(a[0]), "r"(a[1]), "r"(a[2]), "r"(a[3]), "r"(b0), "r"(b1));
}

__device__ __forceinline__ float fast_exp2(float x) {
    float r;
    asm("ex2.approx.ftz.f32 %0, %1;" : "=f"(r) : "f"(x));
    return r;
}

__device__ __forceinline__ uint32_t pack_h2(float a, float b) {
    uint32_t r;
    asm("{ .reg .b16 l, h;\n\t"
        "cvt.rn.f16.f32 l, %1;\n\t"
        "cvt.rn.f16.f32 h, %2;\n\t"
        "mov.b32 %0, {l, h}; }" : "=r"(r) : "f"(a), "f"(b));
    return r;
}

// ---------------------------------------------------------------------------
// Kernel 1: L2-normalize -> fp16, class id, zero accumulators. Warp per row.
// ---------------------------------------------------------------------------
__global__ void __launch_bounds__(256)
normalize_kernel(const float* __restrict__ feats,
                 const float* __restrict__ labels) {
    const int wid = threadIdx.x >> 5;
    const int lane = threadIdx.x & 31;
    const int row = blockIdx.x * 8 + wid;

    float4 v[4];
    float ss = 0.0f;
#pragma unroll
    for (int k = 0; k < 4; k++) {
        v[k] = ((const float4*)(feats + row * DIM))[k * 32 + lane];
        ss += v[k].x * v[k].x + v[k].y * v[k].y + v[k].z * v[k].z + v[k].w * v[k].w;
    }
#pragma unroll
    for (int o = 16; o > 0; o >>= 1) ss += __shfl_xor_sync(0xffffffffu, ss, o);
    float inv = 1.0f / sqrtf(ss);

#pragma unroll
    for (int k = 0; k < 4; k++) {
        uint2 u;
        u.x = pack_h2(v[k].x * inv, v[k].y * inv);
        u.y = pack_h2(v[k].z * inv, v[k].w * inv);
        ((uint2*)(g_normh + row * DIM))[k * 32 + lane] = u;
    }

    if (lane < NCLS) {
        if (labels[row * NCLS + lane] > 0.5f) g_cls[row] = lane;
    }
    if (lane == 0) { g_pos[row] = 0.0f; g_all[row] = 0.0f; }
}

// ---------------------------------------------------------------------------
// Kernel 2: fp16 m16n8k16 symmetric Gram tile, 4-stage cp.async pipeline,
// register-only epilogue. 8 warps (2x4); warp tile 64x32.
// ---------------------------------------------------------------------------
__global__ void __launch_bounds__(256, 2)
contrastive_mma_kernel() {
    extern __shared__ char smem[];
    __shared__ int clsA_s[128];
    __shared__ int clsB_s[128];
    const uint32_t sb = smem_u32(smem);

    const int tid = threadIdx.x;
    const int lane = tid & 31;
    const int wid = tid >> 5;
    const int wr = wid >> 2;        // 0..1 warp row
    const int wc = wid & 3;         // 0..3 warp col
    const int g = lane >> 2;        // 0..7
    const int tig = lane & 3;       // 0..3

    // map linear block index -> upper-triangular (by, bx), bx >= by
    int rem = blockIdx.x;
    int by = 0;
    while (rem >= (NBLK - by)) { rem -= (NBLK - by); by++; }
    const int bx = by + rem;
    const bool isDiag = (bx == by);
    const int rowBase = by * BM;
    const int colBase = bx * BM;

    if (tid < 128) clsA_s[tid] = g_cls[rowBase + tid];
    else           clsB_s[tid - 128] = g_cls[colBase + (tid - 128)];

    // per-lane ldmatrix offsets (bytes within tile)
    const int mA = lane >> 3;       // matrix index 0..3
    const int rA = lane & 7;
    const uint32_t aOff = (uint32_t)((wr * 64 + (mA & 1) * 8 + rA) * RSTRIDE
                                     + (mA >> 1) * 16);
    const uint32_t bOff = (uint32_t)((wc * 32 + (mA >> 1) * 8 + rA) * RSTRIDE
                                     + (mA & 1) * 16);

    float acc[4][4][4];
#pragma unroll
    for (int mi = 0; mi < 4; mi++)
#pragma unroll
        for (int ni = 0; ni < 4; ni++)
#pragma unroll
            for (int r = 0; r < 4; r++) acc[mi][ni][r] = 0.0f;

    auto load_chunk = [&](int c) {
        const int buf = c & (NSTAGE - 1);
        const int k0 = c * KCHUNK;
#pragma unroll
        for (int it = 0; it < 4; it++) {
            int flat = it * 256 + tid;      // 0..1023 16B segments
            int tile = flat >> 9;           // 0 = A, 1 = B
            if (tile == 1 && isDiag) continue;   // diag: B aliases A
            int r = (flat >> 2) & 127;
            int seg = flat & 3;
            const __half* src = g_normh
                + (size_t)((tile ? colBase : rowBase) + r) * DIM + k0 + seg * 8;
            uint32_t dst = sb + (tile ? BBUF(buf) : ABUF(buf))
                         + r * RSTRIDE + seg * 16;
            asm volatile("cp.async.cg.shared.global [%0], [%1], 16;"
                         :: "r"(dst), "l"(src) : "memory");
        }
        asm volatile("cp.async.commit_group;" ::: "memory");
    };

    auto compute_chunk = [&](int buf) {
        const uint32_t aBase = sb + ABUF(buf) + aOff;
        const uint32_t bBase = (isDiag ? sb + ABUF(buf) : sb + BBUF(buf)) + bOff;
#pragma unroll
        for (int ks = 0; ks < 2; ks++) {       // two k16 steps per 32-chunk
            uint32_t a[4][4], b[2][4];
#pragma unroll
            for (int mi = 0; mi < 4; mi++)
                LDSM_X4(a[mi], aBase + mi * (16 * RSTRIDE) + ks * 32);
#pragma unroll
            for (int p = 0; p < 2; p++)        // ni pair p covers ni=2p,2p+1
                LDSM_X4(b[p], bBase + p * (16 * RSTRIDE) + ks * 32);
#pragma unroll
            for (int mi = 0; mi < 4; mi++)
#pragma unroll
                for (int ni = 0; ni < 4; ni++)
                    mma_f16(acc[mi][ni], a[mi],
                            b[ni >> 1][2 * (ni & 1)], b[ni >> 1][2 * (ni & 1) + 1]);
        }
    };

    // ---- 4-stage pipelined mainloop: one __syncthreads per chunk ----
    load_chunk(0);
    load_chunk(1);
    load_chunk(2);
    for (int c = 0; c < NCHUNK; c++) {
        if (c < NCHUNK - 2)
            asm volatile("cp.async.wait_group 2;" ::: "memory");
        else if (c == NCHUNK - 2)
            asm volatile("cp.async.wait_group 1;" ::: "memory");
        else
            asm volatile("cp.async.wait_group 0;" ::: "memory");
        __syncthreads();
        if (c + 3 < NCHUNK) load_chunk(c + 3);
        compute_chunk(c & (NSTAGE - 1));
    }

    // ---- register-only epilogue ----
    const float SCL  = 1.44269504088896f / 0.07f;   // exp(x/T) = exp2(x*SCL)
    const float CLIP = 20.0f * 1.44269504088896f;

    int rcls[4][2], ccls[4][2];
#pragma unroll
    for (int mi = 0; mi < 4; mi++)
#pragma unroll
        for (int h = 0; h < 2; h++)
            rcls[mi][h] = clsA_s[wr * 64 + mi * 16 + h * 8 + g];
#pragma unroll
    for (int ni = 0; ni < 4; ni++)
#pragma unroll
        for (int q = 0; q < 2; q++)
            ccls[ni][q] = clsB_s[wc * 32 + ni * 8 + tig * 2 + q];

    float rAll[4][2], rPos[4][2], cAll[4][2], cPos[4][2];
#pragma unroll
    for (int i = 0; i < 4; i++)
#pragma unroll
        for (int h = 0; h < 2; h++) {
            rAll[i][h] = 0.0f; rPos[i][h] = 0.0f;
            cAll[i][h] = 0.0f; cPos[i][h] = 0.0f;
        }

#pragma unroll
    for (int mi = 0; mi < 4; mi++)
#pragma unroll
        for (int ni = 0; ni < 4; ni++)
#pragma unroll
            for (int h = 0; h < 2; h++)
#pragma unroll
                for (int q = 0; q < 2; q++) {
                    float v = acc[mi][ni][h * 2 + q];
                    float s = fminf(fmaxf(v * SCL, -CLIP), CLIP);
                    float e = fast_exp2(s);
                    if (isDiag) {
                        int rl = wr * 64 + mi * 16 + h * 8 + g;
                        int cl = wc * 32 + ni * 8 + tig * 2 + q;
                        if (rl == cl) e = 0.0f;
                    }
                    rAll[mi][h] += e;
                    cAll[ni][q] += e;
                    if (rcls[mi][h] == ccls[ni][q]) {
                        rPos[mi][h] += e;
                        cPos[ni][q] += e;
                    }
                }

    // row sums: reduce over tig (lane bits 0,1)
#pragma unroll
    for (int mi = 0; mi < 4; mi++)
#pragma unroll
        for (int h = 0; h < 2; h++) {
#pragma unroll
            for (int o = 1; o < 4; o <<= 1) {
                rAll[mi][h] += __shfl_xor_sync(0xffffffffu, rAll[mi][h], o);
                rPos[mi][h] += __shfl_xor_sync(0xffffffffu, rPos[mi][h], o);
            }
        }
    if (tig == 0) {
#pragma unroll
        for (int mi = 0; mi < 4; mi++)
#pragma unroll
            for (int h = 0; h < 2; h++) {
                int gr = rowBase + wr * 64 + mi * 16 + h * 8 + g;
                atomicAdd(&g_all[gr], rAll[mi][h]);
                atomicAdd(&g_pos[gr], rPos[mi][h]);
            }
    }

    // symmetric column sums (off-diagonal only): reduce over g (lane bits 2..4)
    if (!isDiag) {
#pragma unroll
        for (int ni = 0; ni < 4; ni++)
#pragma unroll
            for (int q = 0; q < 2; q++) {
#pragma unroll
                for (int o = 4; o < 32; o <<= 1) {
                    cAll[ni][q] += __shfl_xor_sync(0xffffffffu, cAll[ni][q], o);
                    cPos[ni][q] += __shfl_xor_sync(0xffffffffu, cPos[ni][q], o);
                }
            }
        if (g == 0) {
#pragma unroll
            for (int ni = 0; ni < 4; ni++)
#pragma unroll
                for (int q = 0; q < 2; q++) {
                    int gc = colBase + wc * 32 + ni * 8 + tig * 2 + q;
                    atomicAdd(&g_all[gc], cAll[ni][q]);
                    atomicAdd(&g_pos[gc], cPos[ni][q]);
                }
        }
    }
}

// ---------------------------------------------------------------------------
// Kernel 3: per-row loss + validity + mean  (single block, 1024 threads)
// ---------------------------------------------------------------------------
__global__ void finalize_kernel(float* __restrict__ out) {
    __shared__ int cnt[NCLS];
    __shared__ float s_tot[32];
    __shared__ float s_cnt[32];
    int t = threadIdx.x;  // 1024

    if (t < NCLS) cnt[t] = 0;
    __syncthreads();
    for (int r = t; r < BATCH; r += 1024) atomicAdd(&cnt[g_cls[r]], 1);
    __syncthreads();

    float total = 0.0f, nval = 0.0f;
    for (int r = t; r < BATCH; r += 1024) {
        int c = g_cls[r];
        if (cnt[c] >= 2) {
            float pos = g_pos[r];
            float all = g_all[r];
            float li = -logf(pos / (all + 1e-8f) + 1e-8f);
            total += li;
            nval += 1.0f;
        }
    }
#pragma unroll
    for (int o = 16; o > 0; o >>= 1) {
        total += __shfl_xor_sync(0xffffffffu, total, o);
        nval  += __shfl_xor_sync(0xffffffffu, nval, o);
    }
    if ((t & 31) == 0) { s_tot[t >> 5] = total; s_cnt[t >> 5] = nval; }
    __syncthreads();
    if (t == 0) {
        float tt = 0.0f, nn = 0.0f;
#pragma unroll
        for (int w = 0; w < 32; w++) { tt += s_tot[w]; nn += s_cnt[w]; }
        out[0] = (nn > 0.0f) ? tt / nn : 0.0f;
    }
}

// ---------------------------------------------------------------------------
extern "C" void kernel_launch(void* const* d_in, const int* in_sizes, int n_in,
                              void* d_out, int out_size) {
    const float* features = (const float*)d_in[0];  // [4096, 512] f32
    const float* labels   = (const float*)d_in[1];  // [4096, 10]  f32
    float* out = (float*)d_out;

    cudaFuncSetAttribute(contrastive_mma_kernel,
                         cudaFuncAttributeMaxDynamicSharedMemorySize, SMEM_DYN);

    normalize_kernel<<<BATCH / 8, 256>>>(features, labels);
    contrastive_mma_kernel<<<NTRI, 256, SMEM_DYN>>>();
    finalize_kernel<<<1, 1024>>>(out);
}